// round 2
// baseline (speedup 1.0000x reference)
#include <cuda_runtime.h>
#include <math.h>

#define NE 50000
#define NEP 50048            // NE padded to 64
#define NN 25000
#define NG 1024
#define HID 128

// ---------------- scratch (device globals; no runtime allocation) ----------
__device__ float g_hT[HID * NEP];    // edge MLP hidden, k-major (transposed)
__device__ float g_xa[NN * 64];      // node feature ping
__device__ float g_xb[NN * 64];      // node feature pong
__device__ float g_acc[NN * 64];     // accumulation buffer (root + scatter)
__device__ float g_sums[NG * 64];
__device__ float g_cnt[NG];
__device__ int   g_src[NE];
__device__ int   g_dst[NE];
__device__ int   g_batch[NN];
__device__ int   g_is64;

__device__ __forceinline__ float eluf(float v) { return v > 0.f ? v : expm1f(v); }

#define FMA2(acc, a, b) \
    asm("fma.rn.f32x2 %0, %1, %2, %0;" : "+l"(acc) : "l"(a), "l"(b))
#define UNPACK2(lo, hi, v) \
    asm("mov.b64 {%0, %1}, %2;" : "=f"(lo), "=f"(hi) : "l"(v))

// ---------------- index dtype detection + conversion ----------------------
__global__ void detect_kernel(const long long* __restrict__ ei) {
    if (blockIdx.x == 0 && threadIdx.x == 0) {
        int is64 = 1;
        for (int i = 0; i < 256; i++) {
            long long v = ei[i];
            if (v < 0 || v >= (long long)NN) { is64 = 0; break; }
        }
        g_is64 = is64;
    }
}

__global__ void convert_kernel(const void* __restrict__ ei, const void* __restrict__ bat) {
    int t = blockIdx.x * blockDim.x + threadIdx.x;
    const int is64 = g_is64;
    if (t < NE) {
        if (is64) {
            g_src[t] = (int)((const long long*)ei)[t];
            g_dst[t] = (int)((const long long*)ei)[NE + t];
        } else {
            g_src[t] = ((const int*)ei)[t];
            g_dst[t] = ((const int*)ei)[NE + t];
        }
    }
    if (t < NN) {
        g_batch[t] = is64 ? (int)((const long long*)bat)[t] : ((const int*)bat)[t];
    }
}

// ---------------- edge MLP: hT[k][e] = relu(edge_attr @ w1 + b1) -----------
// k-major output so the msg kernel reads h coalesced per-k.
__global__ void edge_h_kernel(const float* __restrict__ ea,
                              const float* __restrict__ w1,
                              const float* __restrict__ b1) {
    int t = blockIdx.x * blockDim.x + threadIdx.x;
    if (t >= HID * NE) return;
    int k = t / NE, e = t - k * NE;
    const float* a = ea + e * 5;
    float s = b1[k];
#pragma unroll
    for (int d = 0; d < 5; d++) s = fmaf(a[d], w1[d * HID + k], s);
    g_hT[k * NEP + e] = fmaxf(s, 0.f);
}

// ---------------- acc = x @ root + bias (zero-inits the scatter target) ----
template<int M_IN, int M_OUT>
__global__ void root_kernel(const float* __restrict__ x,
                            const float* __restrict__ root,
                            const float* __restrict__ bias,
                            float* __restrict__ acc) {
    int t = blockIdx.x * blockDim.x + threadIdx.x;
    if (t >= NN * M_OUT) return;
    int n = t / M_OUT, o = t - n * M_OUT;
    const float* xr = x + n * M_IN;
    float s = bias[o];
#pragma unroll
    for (int i = 0; i < M_IN; i++) s = fmaf(xr[i], root[i * M_OUT + o], s);
    acc[t] = s;
}

__global__ void elu_kernel(const float* __restrict__ acc, float* __restrict__ xo, int n) {
    int t = blockIdx.x * blockDim.x + threadIdx.x;
    if (t < n) xo[t] = eluf(acc[t]);
}

// ---------------- fused per-edge message GEMM + scatter --------------------
// msg[e,o] = sum_{k,i} h[e,k]*x[src,i]*w2[k,i,o] + sum_i x[src,i]*b2[i,o]
//
// Packed-f32x2 formulation with ZERO pack instructions in the hot loop:
//   - u2_s[i][e] holds (u,u) duplicated pairs -> LDS.128 gives 2 ready b64
//     broadcast operands (edges e, e+1).
//   - w2 output pairs (o,o+1) come free as b64 halves of a 16B global load.
//   - a2[r][q] accumulates edge eb+r, outputs (ob+2q, ob+2q+1).
// Per i-step (RE=4): 16 fma.rn.f32x2 + 2 LDS.128 + 2 LDG.128 -> FMA-pipe bound.
template<int M_IN, int M_OUT, int I_TILE>
__global__ void __launch_bounds__(128)
msg_kernel(const float* __restrict__ xin,
           const float* __restrict__ w2,
           const float* __restrict__ b2,
           float* __restrict__ acc) {
    constexpr int TM  = 64;
    constexpr int QO  = 8;
    constexpr int TX  = M_OUT / QO;      // 4 (L1) or 8 (L2/L3)
    constexpr int NTY = 128 / TX;        // 32 or 16
    constexpr int RE  = TM / NTY;        // 2 or 4
    constexpr int NIH = M_IN / I_TILE;   // I_TILE divides M_IN

    __shared__ __align__(16) float  x_T[M_IN * TM];     // [i][e]
    __shared__ __align__(16) float2 u2_s[I_TILE * TM];  // [i][e] dup pairs
    __shared__ int src_s[TM];
    __shared__ int dst_s[TM];

    const int tid  = threadIdx.x;
    const int e0   = blockIdx.x * TM;
    const int ecnt = min(TM, NE - e0);

    if (tid < TM) {
        src_s[tid] = (tid < ecnt) ? g_src[e0 + tid] : 0;
        dst_s[tid] = (tid < ecnt) ? g_dst[e0 + tid] : -1;
    }
    __syncthreads();
    for (int t = tid; t < M_IN * TM; t += 128) {
        int i = t / TM, e = t - i * TM;
        x_T[t] = (e < ecnt) ? xin[src_s[e] * M_IN + i] : 0.f;
    }
    // first __syncthreads inside the k-loop orders x_T before use

    const int tx  = tid % TX;
    const int ty  = tid / TX;
    const int ob  = tx * QO;
    const int eb  = ty * RE;
    const int eme = tid & (TM - 1);   // build-lane edge (fixed per thread)
    const int ib0 = tid >> 6;         // 0 or 1: build covers 2 i's per pass

    unsigned long long a2[RE][QO / 2];
#pragma unroll
    for (int r = 0; r < RE; r++)
#pragma unroll
        for (int q = 0; q < QO / 2; q++) a2[r][q] = 0ull;

    for (int k = 0; k < HID; k++) {
        const float h_e = g_hT[k * NEP + e0 + eme];   // coalesced/broadcast
        const float* w2k = w2 + k * (M_IN * M_OUT);
#pragma unroll
        for (int ih = 0; ih < NIH; ih++) {
            const int i0 = ih * I_TILE;
            __syncthreads();            // prior readers done with u2_s
#pragma unroll
            for (int i = ib0; i < I_TILE; i += 2) {
                float u = h_e * x_T[(i0 + i) * TM + eme];
                u2_s[i * TM + eme] = make_float2(u, u);
            }
            __syncthreads();
#pragma unroll 4
            for (int i = 0; i < I_TILE; i++) {
                const ulonglong2 uA = *(const ulonglong2*)(u2_s + i * TM + eb);
                const ulonglong2* wp =
                    (const ulonglong2*)(w2k + (i0 + i) * M_OUT + ob);
                const ulonglong2 w01 = wp[0];
                const ulonglong2 w23 = wp[1];
                unsigned long long wq[4] = {w01.x, w01.y, w23.x, w23.y};
#pragma unroll
                for (int q = 0; q < 4; q++) FMA2(a2[0][q], uA.x, wq[q]);
#pragma unroll
                for (int q = 0; q < 4; q++) FMA2(a2[1][q], uA.y, wq[q]);
                if constexpr (RE == 4) {
                    const ulonglong2 uB =
                        *(const ulonglong2*)(u2_s + i * TM + eb + 2);
#pragma unroll
                    for (int q = 0; q < 4; q++) FMA2(a2[2][q], uB.x, wq[q]);
#pragma unroll
                    for (int q = 0; q < 4; q++) FMA2(a2[3][q], uB.y, wq[q]);
                }
            }
        }
    }

    // unpack accumulators
    float av[RE][QO];
#pragma unroll
    for (int r = 0; r < RE; r++)
#pragma unroll
        for (int q = 0; q < QO / 2; q++)
            UNPACK2(av[r][2 * q], av[r][2 * q + 1], a2[r][q]);

    // b2 term: msg += sum_i x[e,i]*b2[i,o]  (tiny, scalar fp32)
#pragma unroll 8
    for (int i = 0; i < M_IN; i++) {
        const float4 b0 = *(const float4*)(b2 + i * M_OUT + ob);
        const float4 b1 = *(const float4*)(b2 + i * M_OUT + ob + 4);
        const float bq[8] = {b0.x, b0.y, b0.z, b0.w, b1.x, b1.y, b1.z, b1.w};
#pragma unroll
        for (int r = 0; r < RE; r++) {
            const float xv = x_T[i * TM + eb + r];
#pragma unroll
            for (int q = 0; q < QO; q++) av[r][q] = fmaf(xv, bq[q], av[r][q]);
        }
    }

    // scatter-add epilogue
#pragma unroll
    for (int r = 0; r < RE; r++) {
        const int d = dst_s[eb + r];
        if (d >= 0) {
            float* p = acc + d * M_OUT + ob;
#pragma unroll
            for (int q = 0; q < QO; q++) atomicAdd(p + q, av[r][q]);
        }
    }
}

// ---------------- pooling + final MLP --------------------------------------
__global__ void pool_init_kernel() {
    int t = blockIdx.x * blockDim.x + threadIdx.x;
    if (t < NG * 64) g_sums[t] = 0.f;
    if (t < NG) g_cnt[t] = 0.f;
}

__global__ void pool_kernel(const float* __restrict__ x) {
    int t = blockIdx.x * blockDim.x + threadIdx.x;
    if (t >= NN * 64) return;
    int n = t >> 6, o = t & 63;
    int g = g_batch[n];
    atomicAdd(&g_sums[g * 64 + o], x[t]);
    if (o == 0) atomicAdd(&g_cnt[g], 1.f);
}

__global__ void __launch_bounds__(128)
mlp_kernel(const float* __restrict__ fc1_w, const float* __restrict__ fc1_b,
           const float* __restrict__ fc2_w, const float* __restrict__ fc2_b,
           const float* __restrict__ fc3_w, const float* __restrict__ fc3_b,
           float* __restrict__ out) {
    int g = blockIdx.x * blockDim.x + threadIdx.x;
    if (g >= NG) return;
    float inv = 1.f / fmaxf(g_cnt[g], 1.f);
    const float* srow = g_sums + g * 64;
    float h1[32];
#pragma unroll
    for (int j = 0; j < 32; j++) {
        float s = 0.f;
#pragma unroll
        for (int i = 0; i < 64; i++) s = fmaf(srow[i], fc1_w[i * 32 + j], s);
        h1[j] = eluf(fmaf(s, inv, fc1_b[j]));
    }
    float h2[16];
#pragma unroll
    for (int j = 0; j < 16; j++) {
        float s = fc2_b[j];
#pragma unroll
        for (int i = 0; i < 32; i++) s = fmaf(h1[i], fc2_w[i * 16 + j], s);
        h2[j] = eluf(s);
    }
    float s = fc3_b[0];
#pragma unroll
    for (int i = 0; i < 16; i++) s = fmaf(h2[i], fc3_w[i], s);
    out[g] = s;
}

// ---------------- driver ----------------------------------------------------
extern "C" void kernel_launch(void* const* d_in, const int* in_sizes, int n_in,
                              void* d_out, int out_size) {
    const float* x       = (const float*)d_in[0];
    const void*  ei      = d_in[1];
    const float* ea      = (const float*)d_in[2];
    const void*  bat     = d_in[3];
    const float* c1_w1   = (const float*)d_in[4];
    const float* c1_b1   = (const float*)d_in[5];
    const float* c1_w2   = (const float*)d_in[6];
    const float* c1_b2   = (const float*)d_in[7];
    const float* c1_root = (const float*)d_in[8];
    const float* c1_bias = (const float*)d_in[9];
    const float* c2_w1   = (const float*)d_in[10];
    const float* c2_b1   = (const float*)d_in[11];
    const float* c2_w2   = (const float*)d_in[12];
    const float* c2_b2   = (const float*)d_in[13];
    const float* c2_root = (const float*)d_in[14];
    const float* c2_bias = (const float*)d_in[15];
    const float* c3_w1   = (const float*)d_in[16];
    const float* c3_b1   = (const float*)d_in[17];
    const float* c3_w2   = (const float*)d_in[18];
    const float* c3_b2   = (const float*)d_in[19];
    const float* c3_root = (const float*)d_in[20];
    const float* c3_bias = (const float*)d_in[21];
    const float* fc1_w   = (const float*)d_in[22];
    const float* fc1_b   = (const float*)d_in[23];
    const float* fc2_w   = (const float*)d_in[24];
    const float* fc2_b   = (const float*)d_in[25];
    const float* fc3_w   = (const float*)d_in[26];
    const float* fc3_b   = (const float*)d_in[27];
    float* out = (float*)d_out;

    float *xa, *xb, *acc;
    cudaGetSymbolAddress((void**)&xa,  g_xa);
    cudaGetSymbolAddress((void**)&xb,  g_xb);
    cudaGetSymbolAddress((void**)&acc, g_acc);

    const int msg_blocks = (NE + 63) / 64;

    detect_kernel<<<1, 32>>>((const long long*)ei);
    convert_kernel<<<(NE + 255) / 256, 256>>>(ei, bat);

    // ---- layer 1: 13 -> 32
    edge_h_kernel<<<(NE * HID + 255) / 256, 256>>>(ea, c1_w1, c1_b1);
    root_kernel<13, 32><<<(NN * 32 + 255) / 256, 256>>>(x, c1_root, c1_bias, acc);
    msg_kernel<13, 32, 13><<<msg_blocks, 128>>>(x, c1_w2, c1_b2, acc);
    elu_kernel<<<(NN * 32 + 255) / 256, 256>>>(acc, xa, NN * 32);

    // ---- layer 2: 32 -> 64
    edge_h_kernel<<<(NE * HID + 255) / 256, 256>>>(ea, c2_w1, c2_b1);
    root_kernel<32, 64><<<(NN * 64 + 255) / 256, 256>>>(xa, c2_root, c2_bias, acc);
    msg_kernel<32, 64, 32><<<msg_blocks, 128>>>(xa, c2_w2, c2_b2, acc);
    elu_kernel<<<(NN * 64 + 255) / 256, 256>>>(acc, xb, NN * 64);

    // ---- layer 3: 64 -> 64
    edge_h_kernel<<<(NE * HID + 255) / 256, 256>>>(ea, c3_w1, c3_b1);
    root_kernel<64, 64><<<(NN * 64 + 255) / 256, 256>>>(xb, c3_root, c3_bias, acc);
    msg_kernel<64, 64, 32><<<msg_blocks, 128>>>(xb, c3_w2, c3_b2, acc);
    elu_kernel<<<(NN * 64 + 255) / 256, 256>>>(acc, xa, NN * 64);

    // ---- pooling + head
    pool_init_kernel<<<(NG * 64 + 255) / 256, 256>>>();
    pool_kernel<<<(NN * 64 + 255) / 256, 256>>>(xa);
    mlp_kernel<<<(NG + 127) / 128, 128>>>(fc1_w, fc1_b, fc2_w, fc2_b, fc3_w, fc3_b, out);
}

// round 3
// speedup vs baseline: 1.0004x; 1.0004x over previous
#include <cuda_runtime.h>
#include <math.h>

#define NE 50000
#define NEP 50048            // NE padded to 64
#define NN 25000
#define NG 1024
#define HID 128

// ---------------- scratch (device globals; no runtime allocation) ----------
__device__ float g_hT[HID * NEP];    // edge MLP hidden, k-major (transposed)
__device__ float g_xa[NN * 64];      // node feature ping
__device__ float g_xb[NN * 64];      // node feature pong
__device__ float g_acc[NN * 64];     // accumulation buffer (root + scatter)
__device__ float g_sums[NG * 64];
__device__ float g_cnt[NG];
__device__ int   g_src[NE];
__device__ int   g_dst[NE];
__device__ int   g_batch[NN];
__device__ int   g_is64;

__device__ __forceinline__ float eluf(float v) { return v > 0.f ? v : expm1f(v); }

#define FMA2(acc, a, b) \
    asm("fma.rn.f32x2 %0, %1, %2, %0;" : "+l"(acc) : "l"(a), "l"(b))
#define UNPACK2(lo, hi, v) \
    asm("mov.b64 {%0, %1}, %2;" : "=f"(lo), "=f"(hi) : "l"(v))

// ---------------- index dtype detection + conversion ----------------------
__global__ void detect_kernel(const long long* __restrict__ ei) {
    if (blockIdx.x == 0 && threadIdx.x == 0) {
        int is64 = 1;
        for (int i = 0; i < 256; i++) {
            long long v = ei[i];
            if (v < 0 || v >= (long long)NN) { is64 = 0; break; }
        }
        g_is64 = is64;
    }
}

__global__ void convert_kernel(const void* __restrict__ ei, const void* __restrict__ bat) {
    int t = blockIdx.x * blockDim.x + threadIdx.x;
    const int is64 = g_is64;
    if (t < NE) {
        if (is64) {
            g_src[t] = (int)((const long long*)ei)[t];
            g_dst[t] = (int)((const long long*)ei)[NE + t];
        } else {
            g_src[t] = ((const int*)ei)[t];
            g_dst[t] = ((const int*)ei)[NE + t];
        }
    }
    if (t < NN) {
        g_batch[t] = is64 ? (int)((const long long*)bat)[t] : ((const int*)bat)[t];
    }
}

// ---------------- edge MLP: hT[k][e] = relu(edge_attr @ w1 + b1) -----------
// k-major output so the msg kernel reads h coalesced per-k.
__global__ void edge_h_kernel(const float* __restrict__ ea,
                              const float* __restrict__ w1,
                              const float* __restrict__ b1) {
    int t = blockIdx.x * blockDim.x + threadIdx.x;
    if (t >= HID * NE) return;
    int k = t / NE, e = t - k * NE;
    const float* a = ea + e * 5;
    float s = b1[k];
#pragma unroll
    for (int d = 0; d < 5; d++) s = fmaf(a[d], w1[d * HID + k], s);
    g_hT[k * NEP + e] = fmaxf(s, 0.f);
}

// ---------------- acc = x @ root + bias (zero-inits the scatter target) ----
template<int M_IN, int M_OUT>
__global__ void root_kernel(const float* __restrict__ x,
                            const float* __restrict__ root,
                            const float* __restrict__ bias,
                            float* __restrict__ acc) {
    int t = blockIdx.x * blockDim.x + threadIdx.x;
    if (t >= NN * M_OUT) return;
    int n = t / M_OUT, o = t - n * M_OUT;
    const float* xr = x + n * M_IN;
    float s = bias[o];
#pragma unroll
    for (int i = 0; i < M_IN; i++) s = fmaf(xr[i], root[i * M_OUT + o], s);
    acc[t] = s;
}

__global__ void elu_kernel(const float* __restrict__ acc, float* __restrict__ xo, int n) {
    int t = blockIdx.x * blockDim.x + threadIdx.x;
    if (t < n) xo[t] = eluf(acc[t]);
}

// ---------------- fused per-edge message GEMM + scatter --------------------
// msg[e,o] = sum_{k,i} h[e,k]*x[src,i]*w2[k,i,o] + sum_i x[src,i]*b2[i,o]
//
// Packed-f32x2 formulation with ZERO pack instructions in the hot loop:
//   - u2_s[i][e] holds (u,u) duplicated pairs -> LDS.128 gives 2 ready b64
//     broadcast operands (edges e, e+1).
//   - w2 output pairs (o,o+1) come free as b64 halves of a 16B global load.
//   - a2[r][q] accumulates edge eb+r, outputs (ob+2q, ob+2q+1).
// Per i-step (RE=4): 16 fma.rn.f32x2 + 2 LDS.128 + 2 LDG.128 -> FMA-pipe bound.
template<int M_IN, int M_OUT, int I_TILE>
__global__ void __launch_bounds__(128)
msg_kernel(const float* __restrict__ xin,
           const float* __restrict__ w2,
           const float* __restrict__ b2,
           float* __restrict__ acc) {
    constexpr int TM  = 64;
    constexpr int QO  = 8;
    constexpr int TX  = M_OUT / QO;      // 4 (L1) or 8 (L2/L3)
    constexpr int NTY = 128 / TX;        // 32 or 16
    constexpr int RE  = TM / NTY;        // 2 or 4
    constexpr int NIH = M_IN / I_TILE;   // I_TILE divides M_IN

    __shared__ __align__(16) float  x_T[M_IN * TM];     // [i][e]
    __shared__ __align__(16) float2 u2_s[I_TILE * TM];  // [i][e] dup pairs
    __shared__ int src_s[TM];
    __shared__ int dst_s[TM];

    const int tid  = threadIdx.x;
    const int e0   = blockIdx.x * TM;
    const int ecnt = min(TM, NE - e0);

    if (tid < TM) {
        src_s[tid] = (tid < ecnt) ? g_src[e0 + tid] : 0;
        dst_s[tid] = (tid < ecnt) ? g_dst[e0 + tid] : -1;
    }
    __syncthreads();
    for (int t = tid; t < M_IN * TM; t += 128) {
        int i = t / TM, e = t - i * TM;
        x_T[t] = (e < ecnt) ? xin[src_s[e] * M_IN + i] : 0.f;
    }
    // first __syncthreads inside the k-loop orders x_T before use

    const int tx  = tid % TX;
    const int ty  = tid / TX;
    const int ob  = tx * QO;
    const int eb  = ty * RE;
    const int eme = tid & (TM - 1);   // build-lane edge (fixed per thread)
    const int ib0 = tid >> 6;         // 0 or 1: build covers 2 i's per pass

    unsigned long long a2[RE][QO / 2];
#pragma unroll
    for (int r = 0; r < RE; r++)
#pragma unroll
        for (int q = 0; q < QO / 2; q++) a2[r][q] = 0ull;

    for (int k = 0; k < HID; k++) {
        const float h_e = g_hT[k * NEP + e0 + eme];   // coalesced/broadcast
        const float* w2k = w2 + k * (M_IN * M_OUT);
#pragma unroll
        for (int ih = 0; ih < NIH; ih++) {
            const int i0 = ih * I_TILE;
            __syncthreads();            // prior readers done with u2_s
#pragma unroll
            for (int i = ib0; i < I_TILE; i += 2) {
                float u = h_e * x_T[(i0 + i) * TM + eme];
                u2_s[i * TM + eme] = make_float2(u, u);
            }
            __syncthreads();
#pragma unroll 4
            for (int i = 0; i < I_TILE; i++) {
                const ulonglong2 uA = *(const ulonglong2*)(u2_s + i * TM + eb);
                const ulonglong2* wp =
                    (const ulonglong2*)(w2k + (i0 + i) * M_OUT + ob);
                const ulonglong2 w01 = wp[0];
                const ulonglong2 w23 = wp[1];
                unsigned long long wq[4] = {w01.x, w01.y, w23.x, w23.y};
#pragma unroll
                for (int q = 0; q < 4; q++) FMA2(a2[0][q], uA.x, wq[q]);
#pragma unroll
                for (int q = 0; q < 4; q++) FMA2(a2[1][q], uA.y, wq[q]);
                if constexpr (RE == 4) {
                    const ulonglong2 uB =
                        *(const ulonglong2*)(u2_s + i * TM + eb + 2);
#pragma unroll
                    for (int q = 0; q < 4; q++) FMA2(a2[2][q], uB.x, wq[q]);
#pragma unroll
                    for (int q = 0; q < 4; q++) FMA2(a2[3][q], uB.y, wq[q]);
                }
            }
        }
    }

    // unpack accumulators
    float av[RE][QO];
#pragma unroll
    for (int r = 0; r < RE; r++)
#pragma unroll
        for (int q = 0; q < QO / 2; q++)
            UNPACK2(av[r][2 * q], av[r][2 * q + 1], a2[r][q]);

    // b2 term: msg += sum_i x[e,i]*b2[i,o]  (tiny, scalar fp32)
#pragma unroll 8
    for (int i = 0; i < M_IN; i++) {
        const float4 b0 = *(const float4*)(b2 + i * M_OUT + ob);
        const float4 b1 = *(const float4*)(b2 + i * M_OUT + ob + 4);
        const float bq[8] = {b0.x, b0.y, b0.z, b0.w, b1.x, b1.y, b1.z, b1.w};
#pragma unroll
        for (int r = 0; r < RE; r++) {
            const float xv = x_T[i * TM + eb + r];
#pragma unroll
            for (int q = 0; q < QO; q++) av[r][q] = fmaf(xv, bq[q], av[r][q]);
        }
    }

    // scatter-add epilogue
#pragma unroll
    for (int r = 0; r < RE; r++) {
        const int d = dst_s[eb + r];
        if (d >= 0) {
            float* p = acc + d * M_OUT + ob;
#pragma unroll
            for (int q = 0; q < QO; q++) atomicAdd(p + q, av[r][q]);
        }
    }
}

// ---------------- pooling + final MLP --------------------------------------
__global__ void pool_init_kernel() {
    int t = blockIdx.x * blockDim.x + threadIdx.x;
    if (t < NG * 64) g_sums[t] = 0.f;
    if (t < NG) g_cnt[t] = 0.f;
}

__global__ void pool_kernel(const float* __restrict__ x) {
    int t = blockIdx.x * blockDim.x + threadIdx.x;
    if (t >= NN * 64) return;
    int n = t >> 6, o = t & 63;
    int g = g_batch[n];
    atomicAdd(&g_sums[g * 64 + o], x[t]);
    if (o == 0) atomicAdd(&g_cnt[g], 1.f);
}

__global__ void __launch_bounds__(128)
mlp_kernel(const float* __restrict__ fc1_w, const float* __restrict__ fc1_b,
           const float* __restrict__ fc2_w, const float* __restrict__ fc2_b,
           const float* __restrict__ fc3_w, const float* __restrict__ fc3_b,
           float* __restrict__ out) {
    int g = blockIdx.x * blockDim.x + threadIdx.x;
    if (g >= NG) return;
    float inv = 1.f / fmaxf(g_cnt[g], 1.f);
    const float* srow = g_sums + g * 64;
    float h1[32];
#pragma unroll
    for (int j = 0; j < 32; j++) {
        float s = 0.f;
#pragma unroll
        for (int i = 0; i < 64; i++) s = fmaf(srow[i], fc1_w[i * 32 + j], s);
        h1[j] = eluf(fmaf(s, inv, fc1_b[j]));
    }
    float h2[16];
#pragma unroll
    for (int j = 0; j < 16; j++) {
        float s = fc2_b[j];
#pragma unroll
        for (int i = 0; i < 32; i++) s = fmaf(h1[i], fc2_w[i * 16 + j], s);
        h2[j] = eluf(s);
    }
    float s = fc3_b[0];
#pragma unroll
    for (int i = 0; i < 16; i++) s = fmaf(h2[i], fc3_w[i], s);
    out[g] = s;
}

// ---------------- driver ----------------------------------------------------
extern "C" void kernel_launch(void* const* d_in, const int* in_sizes, int n_in,
                              void* d_out, int out_size) {
    const float* x       = (const float*)d_in[0];
    const void*  ei      = d_in[1];
    const float* ea      = (const float*)d_in[2];
    const void*  bat     = d_in[3];
    const float* c1_w1   = (const float*)d_in[4];
    const float* c1_b1   = (const float*)d_in[5];
    const float* c1_w2   = (const float*)d_in[6];
    const float* c1_b2   = (const float*)d_in[7];
    const float* c1_root = (const float*)d_in[8];
    const float* c1_bias = (const float*)d_in[9];
    const float* c2_w1   = (const float*)d_in[10];
    const float* c2_b1   = (const float*)d_in[11];
    const float* c2_w2   = (const float*)d_in[12];
    const float* c2_b2   = (const float*)d_in[13];
    const float* c2_root = (const float*)d_in[14];
    const float* c2_bias = (const float*)d_in[15];
    const float* c3_w1   = (const float*)d_in[16];
    const float* c3_b1   = (const float*)d_in[17];
    const float* c3_w2   = (const float*)d_in[18];
    const float* c3_b2   = (const float*)d_in[19];
    const float* c3_root = (const float*)d_in[20];
    const float* c3_bias = (const float*)d_in[21];
    const float* fc1_w   = (const float*)d_in[22];
    const float* fc1_b   = (const float*)d_in[23];
    const float* fc2_w   = (const float*)d_in[24];
    const float* fc2_b   = (const float*)d_in[25];
    const float* fc3_w   = (const float*)d_in[26];
    const float* fc3_b   = (const float*)d_in[27];
    float* out = (float*)d_out;

    float *xa, *xb, *acc;
    cudaGetSymbolAddress((void**)&xa,  g_xa);
    cudaGetSymbolAddress((void**)&xb,  g_xb);
    cudaGetSymbolAddress((void**)&acc, g_acc);

    const int msg_blocks = (NE + 63) / 64;

    detect_kernel<<<1, 32>>>((const long long*)ei);
    convert_kernel<<<(NE + 255) / 256, 256>>>(ei, bat);

    // ---- layer 1: 13 -> 32
    edge_h_kernel<<<(NE * HID + 255) / 256, 256>>>(ea, c1_w1, c1_b1);
    root_kernel<13, 32><<<(NN * 32 + 255) / 256, 256>>>(x, c1_root, c1_bias, acc);
    msg_kernel<13, 32, 13><<<msg_blocks, 128>>>(x, c1_w2, c1_b2, acc);
    elu_kernel<<<(NN * 32 + 255) / 256, 256>>>(acc, xa, NN * 32);

    // ---- layer 2: 32 -> 64
    edge_h_kernel<<<(NE * HID + 255) / 256, 256>>>(ea, c2_w1, c2_b1);
    root_kernel<32, 64><<<(NN * 64 + 255) / 256, 256>>>(xa, c2_root, c2_bias, acc);
    msg_kernel<32, 64, 32><<<msg_blocks, 128>>>(xa, c2_w2, c2_b2, acc);
    elu_kernel<<<(NN * 64 + 255) / 256, 256>>>(acc, xb, NN * 64);

    // ---- layer 3: 64 -> 64
    edge_h_kernel<<<(NE * HID + 255) / 256, 256>>>(ea, c3_w1, c3_b1);
    root_kernel<64, 64><<<(NN * 64 + 255) / 256, 256>>>(xb, c3_root, c3_bias, acc);
    msg_kernel<64, 64, 32><<<msg_blocks, 128>>>(xb, c3_w2, c3_b2, acc);
    elu_kernel<<<(NN * 64 + 255) / 256, 256>>>(acc, xa, NN * 64);

    // ---- pooling + head
    pool_init_kernel<<<(NG * 64 + 255) / 256, 256>>>();
    pool_kernel<<<(NN * 64 + 255) / 256, 256>>>(xa);
    mlp_kernel<<<(NG + 127) / 128, 128>>>(fc1_w, fc1_b, fc2_w, fc2_b, fc3_w, fc3_b, out);
}

// round 5
// speedup vs baseline: 4.5088x; 4.5071x over previous
#include <cuda_runtime.h>
#include <cuda_bf16.h>
#include <math.h>
#include <stdint.h>

#define NE 50000
#define NN 25000
#define NG 1024
#define HID 128
#define NTILES 391

// smem layout (dynamic): A hi [128x272B] | A lo | B buf0 (hi|lo) | B buf1 (hi|lo)
#define SM_A_LO   34816          // 128*272
#define SM_B      69632
#define SM_BUF    34816          // 64*272*2
#define SM_B_LO   17408          // 64*272
#define SMEM_BYTES 139264

__device__ __align__(256) unsigned char g_hA[(size_t)NTILES * 65536]; // per-tile: hi 32K | lo 32K
__device__ __align__(256) unsigned char g_w2s[64 * 32768];            // per-chunk: hi 16K | lo 16K
__device__ float g_fa[NN * 64];
__device__ float g_fb[NN * 64];
__device__ float g_acc[NN * 64];
__device__ float g_y[NN * 64];        // x @ b2 per node
__device__ float g_sums[NG * 64];
__device__ float g_cnt[NG];
__device__ int g_src[NE], g_dst[NE], g_batch[NN], g_is64;

__device__ __forceinline__ float eluf(float v) { return v > 0.f ? v : expm1f(v); }
__device__ __forceinline__ uint32_t s2u(const void* p) {
    uint32_t a;
    asm("{ .reg .u64 t; cvta.to.shared.u64 t, %1; cvt.u32.u64 %0, t; }" : "=r"(a) : "l"(p));
    return a;
}
__device__ __forceinline__ void cp16(uint32_t s, const void* g) {
    asm volatile("cp.async.cg.shared.global [%0], [%1], 16;" :: "r"(s), "l"(g));
}
__device__ __forceinline__ void cp_commit() { asm volatile("cp.async.commit_group;" ::: "memory"); }
template<int N> __device__ __forceinline__ void cp_wait() { asm volatile("cp.async.wait_group %0;" :: "n"(N) : "memory"); }
__device__ __forceinline__ void ldsm4(uint32_t* r, uint32_t a) {
    asm volatile("ldmatrix.sync.aligned.m8n8.x4.shared.b16 {%0,%1,%2,%3}, [%4];"
                 : "=r"(r[0]), "=r"(r[1]), "=r"(r[2]), "=r"(r[3]) : "r"(a));
}
__device__ __forceinline__ void mma16816(float* d, const uint32_t* a, uint32_t b0, uint32_t b1) {
    asm volatile("mma.sync.aligned.m16n8k16.row.col.f32.bf16.bf16.f32 "
                 "{%0,%1,%2,%3}, {%4,%5,%6,%7}, {%8,%9}, {%0,%1,%2,%3};"
                 : "+f"(d[0]), "+f"(d[1]), "+f"(d[2]), "+f"(d[3])
                 : "r"(a[0]), "r"(a[1]), "r"(a[2]), "r"(a[3]), "r"(b0), "r"(b1));
}

// ---------------- index dtype detect + convert -----------------------------
__global__ void detect_kernel(const long long* __restrict__ ei) {
    if (blockIdx.x == 0 && threadIdx.x == 0) {
        int is64 = 1;
        for (int i = 0; i < 256; i++) { long long v = ei[i]; if (v < 0 || v >= (long long)NN) { is64 = 0; break; } }
        g_is64 = is64;
    }
}
__global__ void convert_kernel(const void* __restrict__ ei, const void* __restrict__ bat) {
    int t = blockIdx.x * blockDim.x + threadIdx.x;
    const int is64 = g_is64;
    if (t < NE) {
        if (is64) { g_src[t] = (int)((const long long*)ei)[t]; g_dst[t] = (int)((const long long*)ei)[NE + t]; }
        else      { g_src[t] = ((const int*)ei)[t];            g_dst[t] = ((const int*)ei)[NE + t]; }
    }
    if (t < NN) g_batch[t] = is64 ? (int)((const long long*)bat)[t] : ((const int*)bat)[t];
}

// -------- edge MLP -> bf16 hi/lo A tiles (per 128-edge tile, row-major) ----
__global__ void edge_hA_kernel(const float* __restrict__ ea, const float* __restrict__ w1,
                               const float* __restrict__ b1) {
    int t = blockIdx.x * blockDim.x + threadIdx.x;
    if (t >= NE * 64) return;
    int e = t >> 6, k = (t & 63) * 2;
    const float* a = ea + e * 5;
    float s0 = b1[k], s1 = b1[k + 1];
#pragma unroll
    for (int d = 0; d < 5; d++) { float av = a[d]; s0 = fmaf(av, w1[d * HID + k], s0); s1 = fmaf(av, w1[d * HID + k + 1], s1); }
    s0 = fmaxf(s0, 0.f); s1 = fmaxf(s1, 0.f);
    __nv_bfloat16 h0 = __float2bfloat16(s0), h1 = __float2bfloat16(s1);
    __nv_bfloat16 l0 = __float2bfloat16(s0 - __bfloat162float(h0));
    __nv_bfloat16 l1 = __float2bfloat16(s1 - __bfloat162float(h1));
    int tile = e >> 7, row = e & 127;
    unsigned char* base = g_hA + (size_t)tile * 65536;
    uint32_t off = (uint32_t)(row * 256 + k * 2);
    *(uint32_t*)(base + off)         = ((uint32_t)__bfloat16_as_ushort(h1) << 16) | __bfloat16_as_ushort(h0);
    *(uint32_t*)(base + 32768 + off) = ((uint32_t)__bfloat16_as_ushort(l1) << 16) | __bfloat16_as_ushort(l0);
}

// -------- w2 -> bf16 hi/lo B chunk tiles: w2T[n][k], 64 n-rows per chunk ---
template<int M_IN, int M_OUT, int NC>
__global__ void w2prep_kernel(const float* __restrict__ w2) {
    int t = blockIdx.x * blockDim.x + threadIdx.x;
    if (t >= NC * 8192) return;
    int c = t >> 13, rem = t & 8191, r = rem >> 7, k = rem & 127;
    int n = c * 64 + r;
    float v = (n < M_IN * M_OUT) ? w2[k * (M_IN * M_OUT) + n] : 0.f;
    __nv_bfloat16 hi = __float2bfloat16(v);
    __nv_bfloat16 lo = __float2bfloat16(v - __bfloat162float(hi));
    unsigned char* base = g_w2s + (size_t)c * 32768;
    uint32_t off = (uint32_t)(r * 256 + k * 2);
    *(__nv_bfloat16*)(base + off)         = hi;
    *(__nv_bfloat16*)(base + 16384 + off) = lo;
}

// -------- per-node y = x @ b2 ----------------------------------------------
template<int M_IN, int M_OUT>
__global__ void xb2_kernel(const float* __restrict__ x, const float* __restrict__ b2) {
    int t = blockIdx.x * blockDim.x + threadIdx.x;
    if (t >= NN * M_OUT) return;
    int n = t / M_OUT, o = t - n * M_OUT;
    const float* xr = x + n * M_IN;
    float s = 0.f;
#pragma unroll
    for (int i = 0; i < M_IN; i++) s = fmaf(xr[i], b2[i * M_OUT + o], s);
    g_y[t] = s;
}

// -------- acc = x @ root + bias --------------------------------------------
template<int M_IN, int M_OUT>
__global__ void root_kernel(const float* __restrict__ x, const float* __restrict__ root,
                            const float* __restrict__ bias, float* __restrict__ acc) {
    int t = blockIdx.x * blockDim.x + threadIdx.x;
    if (t >= NN * M_OUT) return;
    int n = t / M_OUT, o = t - n * M_OUT;
    const float* xr = x + n * M_IN;
    float s = bias[o];
#pragma unroll
    for (int i = 0; i < M_IN; i++) s = fmaf(xr[i], root[i * M_OUT + o], s);
    acc[t] = s;
}

__global__ void elu_kernel(const float* __restrict__ acc, float* __restrict__ xo, int n) {
    int t = blockIdx.x * blockDim.x + threadIdx.x;
    if (t < n) xo[t] = eluf(acc[t]);
}

// -------- message GEMM (mma.sync bf16, 3-pass split) + contract + scatter --
// Per 128-edge tile: V[e,n] = sum_k h[e,k] * w2T[n,k]  (SS GEMM via HMMA),
// then av[e,o] += x[src_e, i(n)] * V[e,n]; finally atomicAdd into acc[dst_e].
__device__ __forceinline__ void copyB(int c, uint32_t dst, int tid) {
    const unsigned char* gb = g_w2s + (size_t)c * 32768;
    for (int idx = tid; idx < 2048; idx += 256) {
        int half = idx >> 10, r = (idx >> 4) & 63, s = idx & 15;
        cp16(dst + half * SM_B_LO + r * 272 + s * 16, gb + half * 16384 + r * 256 + s * 16);
    }
}

template<int M_IN, int M_OUT, int NC>
__global__ void __launch_bounds__(256, 1)
msg_mma_kernel(const float* __restrict__ xin, float* __restrict__ acc) {
    extern __shared__ char smem[];
    const uint32_t sb = s2u(smem);
    const int tid = threadIdx.x, wid = tid >> 5, lane = tid & 31;

    // prologue: A(hi+lo) + B0 as group0; B1 as group1
    {
        const unsigned char* ga = g_hA + (size_t)blockIdx.x * 65536;
        for (int idx = tid; idx < 4096; idx += 256) {
            int half = idx >> 11, r = (idx >> 4) & 127, s = idx & 15;
            cp16(sb + half * SM_A_LO + r * 272 + s * 16, ga + half * 32768 + r * 256 + s * 16);
        }
        copyB(0, sb + SM_B, tid);
        cp_commit();
        copyB(1, sb + SM_B + SM_BUF, tid);
        cp_commit();
    }

    const int m0 = wid * 16;
    const int r0 = lane >> 2;
    const int e0 = blockIdx.x * 128 + m0 + r0;
    const int e1 = e0 + 8;
    int src0 = 0, dst0 = -1, src1 = 0, dst1 = -1;
    if (e0 < NE) { src0 = g_src[e0]; dst0 = g_dst[e0]; }
    if (e1 < NE) { src1 = g_src[e1]; dst1 = g_dst[e1]; }

    const uint32_t lrow = (lane & 15);
    const uint32_t kh16 = (lane >> 4) * 16;

    float av[8][4];
#pragma unroll
    for (int nb = 0; nb < 8; nb++)
#pragma unroll
        for (int q = 0; q < 4; q++) av[nb][q] = 0.f;

    for (int c = 0; c < NC; c++) {
        if (c + 1 == NC) cp_wait<0>(); else cp_wait<1>();
        __syncthreads();

        const uint32_t bufb = sb + SM_B + (uint32_t)(c & 1) * SM_BUF;
        float d[8][4];
#pragma unroll
        for (int nb = 0; nb < 8; nb++)
#pragma unroll
            for (int q = 0; q < 4; q++) d[nb][q] = 0.f;

#pragma unroll
        for (int p = 0; p < 3; p++) {
            const uint32_t Ab = sb + (p == 1 ? SM_A_LO : 0u);
            const uint32_t Bb = bufb + (p == 2 ? (uint32_t)SM_B_LO : 0u);
#pragma unroll
            for (int ks = 0; ks < 8; ks++) {
                uint32_t a[4];
                ldsm4(a, Ab + (m0 + lrow) * 272 + ks * 32 + kh16);
#pragma unroll
                for (int nb2 = 0; nb2 < 4; nb2++) {
                    uint32_t b[4];
                    ldsm4(b, Bb + (nb2 * 16 + lrow) * 272 + ks * 32 + kh16);
                    mma16816(d[2 * nb2],     a, b[0], b[2]);
                    mma16816(d[2 * nb2 + 1], a, b[1], b[3]);
                }
            }
        }

        // contract chunk with fp32 x
        if constexpr (M_OUT == 64) {
            const float xs0 = xin[(size_t)src0 * M_IN + c];
            const float xs1 = xin[(size_t)src1 * M_IN + c];
#pragma unroll
            for (int nb = 0; nb < 8; nb++) {
                av[nb][0] = fmaf(xs0, d[nb][0], av[nb][0]);
                av[nb][1] = fmaf(xs0, d[nb][1], av[nb][1]);
                av[nb][2] = fmaf(xs1, d[nb][2], av[nb][2]);
                av[nb][3] = fmaf(xs1, d[nb][3], av[nb][3]);
            }
        } else {
            const int i0 = min(2 * c, M_IN - 1), i1 = min(2 * c + 1, M_IN - 1);
            const float x00 = xin[(size_t)src0 * M_IN + i0];
            const float x01 = xin[(size_t)src0 * M_IN + i1];
            const float x10 = xin[(size_t)src1 * M_IN + i0];
            const float x11 = xin[(size_t)src1 * M_IN + i1];
#pragma unroll
            for (int nb = 0; nb < 8; nb++) {
                const float xsa = (nb < 4) ? x00 : x01;
                const float xsb = (nb < 4) ? x10 : x11;
                av[nb][0] = fmaf(xsa, d[nb][0], av[nb][0]);
                av[nb][1] = fmaf(xsa, d[nb][1], av[nb][1]);
                av[nb][2] = fmaf(xsb, d[nb][2], av[nb][2]);
                av[nb][3] = fmaf(xsb, d[nb][3], av[nb][3]);
            }
        }

        __syncthreads();                 // all warps done reading buf before refill
        if (c + 2 < NC) { copyB(c + 2, sb + SM_B + (uint32_t)(c & 1) * SM_BUF, tid); cp_commit(); }
    }

    // scatter-add (+ precomputed x@b2 term)
    const int oc = (lane & 3) * 2;
    if constexpr (M_OUT == 64) {
#pragma unroll
        for (int nb = 0; nb < 8; nb++) {
            const int o = nb * 8 + oc;
            if (dst0 >= 0) {
                atomicAdd(acc + (size_t)dst0 * 64 + o,     av[nb][0] + g_y[(size_t)src0 * 64 + o]);
                atomicAdd(acc + (size_t)dst0 * 64 + o + 1, av[nb][1] + g_y[(size_t)src0 * 64 + o + 1]);
            }
            if (dst1 >= 0) {
                atomicAdd(acc + (size_t)dst1 * 64 + o,     av[nb][2] + g_y[(size_t)src1 * 64 + o]);
                atomicAdd(acc + (size_t)dst1 * 64 + o + 1, av[nb][3] + g_y[(size_t)src1 * 64 + o + 1]);
            }
        }
    } else {
#pragma unroll
        for (int nb = 0; nb < 4; nb++) {
            const int o = nb * 8 + oc;
            if (dst0 >= 0) {
                atomicAdd(acc + (size_t)dst0 * 32 + o,     av[nb][0] + av[nb + 4][0] + g_y[(size_t)src0 * 32 + o]);
                atomicAdd(acc + (size_t)dst0 * 32 + o + 1, av[nb][1] + av[nb + 4][1] + g_y[(size_t)src0 * 32 + o + 1]);
            }
            if (dst1 >= 0) {
                atomicAdd(acc + (size_t)dst1 * 32 + o,     av[nb][2] + av[nb + 4][2] + g_y[(size_t)src1 * 32 + o]);
                atomicAdd(acc + (size_t)dst1 * 32 + o + 1, av[nb][3] + av[nb + 4][3] + g_y[(size_t)src1 * 32 + o + 1]);
            }
        }
    }
}

// ---------------- pooling + final MLP --------------------------------------
__global__ void pool_init_kernel() {
    int t = blockIdx.x * blockDim.x + threadIdx.x;
    if (t < NG * 64) g_sums[t] = 0.f;
    if (t < NG) g_cnt[t] = 0.f;
}
__global__ void pool_kernel(const float* __restrict__ x) {
    int t = blockIdx.x * blockDim.x + threadIdx.x;
    if (t >= NN * 64) return;
    int n = t >> 6, o = t & 63;
    int g = g_batch[n];
    atomicAdd(&g_sums[g * 64 + o], x[t]);
    if (o == 0) atomicAdd(&g_cnt[g], 1.f);
}
__global__ void __launch_bounds__(128)
mlp_kernel(const float* __restrict__ f1w, const float* __restrict__ f1b,
           const float* __restrict__ f2w, const float* __restrict__ f2b,
           const float* __restrict__ f3w, const float* __restrict__ f3b,
           float* __restrict__ out) {
    int g = blockIdx.x * blockDim.x + threadIdx.x;
    if (g >= NG) return;
    float inv = 1.f / fmaxf(g_cnt[g], 1.f);
    const float* sr = g_sums + g * 64;
    float h1[32];
#pragma unroll
    for (int j = 0; j < 32; j++) {
        float s = 0.f;
#pragma unroll
        for (int i = 0; i < 64; i++) s = fmaf(sr[i], f1w[i * 32 + j], s);
        h1[j] = eluf(fmaf(s, inv, f1b[j]));
    }
    float h2[16];
#pragma unroll
    for (int j = 0; j < 16; j++) {
        float s = f2b[j];
#pragma unroll
        for (int i = 0; i < 32; i++) s = fmaf(h1[i], f2w[i * 16 + j], s);
        h2[j] = eluf(s);
    }
    float s = f3b[0];
#pragma unroll
    for (int i = 0; i < 16; i++) s = fmaf(h2[i], f3w[i], s);
    out[g] = s;
}

// ---------------- driver ----------------------------------------------------
extern "C" void kernel_launch(void* const* d_in, const int* in_sizes, int n_in,
                              void* d_out, int out_size) {
    const float* x   = (const float*)d_in[0];
    const void*  ei  = d_in[1];
    const float* ea  = (const float*)d_in[2];
    const void*  bat = d_in[3];
    const float* W[24];
    for (int i = 0; i < 24; i++) W[i] = (const float*)d_in[4 + i];
    float* out = (float*)d_out;

    float *fa, *fb, *acc;
    cudaGetSymbolAddress((void**)&fa, g_fa);
    cudaGetSymbolAddress((void**)&fb, g_fb);
    cudaGetSymbolAddress((void**)&acc, g_acc);

    cudaFuncSetAttribute(msg_mma_kernel<13, 32, 7>,  cudaFuncAttributeMaxDynamicSharedMemorySize, SMEM_BYTES);
    cudaFuncSetAttribute(msg_mma_kernel<32, 64, 32>, cudaFuncAttributeMaxDynamicSharedMemorySize, SMEM_BYTES);
    cudaFuncSetAttribute(msg_mma_kernel<64, 64, 64>, cudaFuncAttributeMaxDynamicSharedMemorySize, SMEM_BYTES);

    detect_kernel<<<1, 32>>>((const long long*)ei);
    convert_kernel<<<(NE + 255) / 256, 256>>>(ei, bat);

    // layer 1: 13 -> 32
    edge_hA_kernel<<<(NE * 64 + 255) / 256, 256>>>(ea, W[0], W[1]);
    w2prep_kernel<13, 32, 7><<<(7 * 8192 + 255) / 256, 256>>>(W[2]);
    xb2_kernel<13, 32><<<(NN * 32 + 255) / 256, 256>>>(x, W[3]);
    root_kernel<13, 32><<<(NN * 32 + 255) / 256, 256>>>(x, W[4], W[5], acc);
    msg_mma_kernel<13, 32, 7><<<NTILES, 256, SMEM_BYTES>>>(x, acc);
    elu_kernel<<<(NN * 32 + 255) / 256, 256>>>(acc, fa, NN * 32);

    // layer 2: 32 -> 64
    edge_hA_kernel<<<(NE * 64 + 255) / 256, 256>>>(ea, W[6], W[7]);
    w2prep_kernel<32, 64, 32><<<(32 * 8192 + 255) / 256, 256>>>(W[8]);
    xb2_kernel<32, 64><<<(NN * 64 + 255) / 256, 256>>>(fa, W[9]);
    root_kernel<32, 64><<<(NN * 64 + 255) / 256, 256>>>(fa, W[10], W[11], acc);
    msg_mma_kernel<32, 64, 32><<<NTILES, 256, SMEM_BYTES>>>(fa, acc);
    elu_kernel<<<(NN * 64 + 255) / 256, 256>>>(acc, fb, NN * 64);

    // layer 3: 64 -> 64
    edge_hA_kernel<<<(NE * 64 + 255) / 256, 256>>>(ea, W[12], W[13]);
    w2prep_kernel<64, 64, 64><<<(64 * 8192 + 255) / 256, 256>>>(W[14]);
    xb2_kernel<64, 64><<<(NN * 64 + 255) / 256, 256>>>(fb, W[15]);
    root_kernel<64, 64><<<(NN * 64 + 255) / 256, 256>>>(fb, W[16], W[17], acc);
    msg_mma_kernel<64, 64, 64><<<NTILES, 256, SMEM_BYTES>>>(fb, acc);
    elu_kernel<<<(NN * 64 + 255) / 256, 256>>>(acc, fa, NN * 64);

    // pooling + head
    pool_init_kernel<<<(NG * 64 + 255) / 256, 256>>>();
    pool_kernel<<<(NN * 64 + 255) / 256, 256>>>(fa);
    mlp_kernel<<<(NG + 127) / 128, 128>>>(W[18], W[19], W[20], W[21], W[22], W[23], out);
}

// round 6
// speedup vs baseline: 6.4444x; 1.4293x over previous
#include <cuda_runtime.h>
#include <cuda_fp16.h>
#include <math.h>
#include <stdint.h>

#define NE 50000
#define NN 25000
#define NG 1024
#define HID 128
#define NTILES 391

// smem layout (dynamic): A [128x272B] | B buf0 (hi|lo) | B buf1 (hi|lo)
#define SM_A_SZ   34816          // 128*272
#define SM_B      34816
#define SM_BUF    34816          // 64*272*2 (hi+lo)
#define SM_B_LO   17408          // 64*272
#define SMEM_BYTES 104448

__device__ __align__(256) unsigned char g_hA[(size_t)NTILES * 32768]; // per-tile fp16 h [128x256B]
__device__ __align__(256) unsigned char g_w2s[64 * 32768];            // per-chunk fp16: hi 16K | lo 16K
__device__ float g_fa[NN * 64];
__device__ float g_fb[NN * 64];
__device__ float g_acc[NN * 64];
__device__ float g_y[NN * 64];        // x @ b2 per node
__device__ float g_sums[NG * 64];
__device__ float g_cnt[NG];
__device__ int g_src[NE], g_dst[NE], g_batch[NN], g_is64;

__device__ __forceinline__ float eluf(float v) { return v > 0.f ? v : expm1f(v); }
__device__ __forceinline__ uint32_t s2u(const void* p) {
    uint32_t a;
    asm("{ .reg .u64 t; cvta.to.shared.u64 t, %1; cvt.u32.u64 %0, t; }" : "=r"(a) : "l"(p));
    return a;
}
__device__ __forceinline__ void cp16(uint32_t s, const void* g) {
    asm volatile("cp.async.cg.shared.global [%0], [%1], 16;" :: "r"(s), "l"(g));
}
__device__ __forceinline__ void cp_commit() { asm volatile("cp.async.commit_group;" ::: "memory"); }
template<int N> __device__ __forceinline__ void cp_wait() { asm volatile("cp.async.wait_group %0;" :: "n"(N) : "memory"); }
__device__ __forceinline__ void ldsm4(uint32_t* r, uint32_t a) {
    asm volatile("ldmatrix.sync.aligned.m8n8.x4.shared.b16 {%0,%1,%2,%3}, [%4];"
                 : "=r"(r[0]), "=r"(r[1]), "=r"(r[2]), "=r"(r[3]) : "r"(a));
}
__device__ __forceinline__ void mma16816(float* d, const uint32_t* a, uint32_t b0, uint32_t b1) {
    asm volatile("mma.sync.aligned.m16n8k16.row.col.f32.f16.f16.f32 "
                 "{%0,%1,%2,%3}, {%4,%5,%6,%7}, {%8,%9}, {%0,%1,%2,%3};"
                 : "+f"(d[0]), "+f"(d[1]), "+f"(d[2]), "+f"(d[3])
                 : "r"(a[0]), "r"(a[1]), "r"(a[2]), "r"(a[3]), "r"(b0), "r"(b1));
}

// ---------------- index dtype detect + convert -----------------------------
__global__ void detect_kernel(const long long* __restrict__ ei) {
    if (blockIdx.x == 0 && threadIdx.x == 0) {
        int is64 = 1;
        for (int i = 0; i < 256; i++) { long long v = ei[i]; if (v < 0 || v >= (long long)NN) { is64 = 0; break; } }
        g_is64 = is64;
    }
}
__global__ void convert_kernel(const void* __restrict__ ei, const void* __restrict__ bat) {
    int t = blockIdx.x * blockDim.x + threadIdx.x;
    const int is64 = g_is64;
    if (t < NE) {
        if (is64) { g_src[t] = (int)((const long long*)ei)[t]; g_dst[t] = (int)((const long long*)ei)[NE + t]; }
        else      { g_src[t] = ((const int*)ei)[t];            g_dst[t] = ((const int*)ei)[NE + t]; }
    }
    if (t < NN) g_batch[t] = is64 ? (int)((const long long*)bat)[t] : ((const int*)bat)[t];
}

// -------- edge MLP -> fp16 A tiles (per 128-edge tile, row-major 256B) -----
__global__ void edge_hA_kernel(const float* __restrict__ ea, const float* __restrict__ w1,
                               const float* __restrict__ b1) {
    int t = blockIdx.x * blockDim.x + threadIdx.x;
    if (t >= NE * 64) return;
    int e = t >> 6, k = (t & 63) * 2;
    const float* a = ea + e * 5;
    float s0 = b1[k], s1 = b1[k + 1];
#pragma unroll
    for (int d = 0; d < 5; d++) { float av = a[d]; s0 = fmaf(av, w1[d * HID + k], s0); s1 = fmaf(av, w1[d * HID + k + 1], s1); }
    s0 = fmaxf(s0, 0.f); s1 = fmaxf(s1, 0.f);
    __half h0 = __float2half(s0), h1 = __float2half(s1);
    int tile = e >> 7, row = e & 127;
    unsigned char* base = g_hA + (size_t)tile * 32768;
    *(uint32_t*)(base + row * 256 + k * 2) =
        ((uint32_t)__half_as_ushort(h1) << 16) | __half_as_ushort(h0);
}

// -------- w2 -> fp16 hi/lo B chunk tiles: w2T[n][k], 64 n-rows per chunk ---
template<int M_IN, int M_OUT, int NC>
__global__ void w2prep_kernel(const float* __restrict__ w2) {
    int t = blockIdx.x * blockDim.x + threadIdx.x;
    if (t >= NC * 8192) return;
    int c = t >> 13, rem = t & 8191, r = rem >> 7, k = rem & 127;
    int n = c * 64 + r;
    float v = (n < M_IN * M_OUT) ? w2[k * (M_IN * M_OUT) + n] : 0.f;
    __half hi = __float2half(v);
    __half lo = __float2half(v - __half2float(hi));
    unsigned char* base = g_w2s + (size_t)c * 32768;
    uint32_t off = (uint32_t)(r * 256 + k * 2);
    *(__half*)(base + off)         = hi;
    *(__half*)(base + 16384 + off) = lo;
}

// -------- per-node y = x @ b2 ----------------------------------------------
template<int M_IN, int M_OUT>
__global__ void xb2_kernel(const float* __restrict__ x, const float* __restrict__ b2) {
    int t = blockIdx.x * blockDim.x + threadIdx.x;
    if (t >= NN * M_OUT) return;
    int n = t / M_OUT, o = t - n * M_OUT;
    const float* xr = x + n * M_IN;
    float s = 0.f;
#pragma unroll
    for (int i = 0; i < M_IN; i++) s = fmaf(xr[i], b2[i * M_OUT + o], s);
    g_y[t] = s;
}

// -------- acc = x @ root + bias --------------------------------------------
template<int M_IN, int M_OUT>
__global__ void root_kernel(const float* __restrict__ x, const float* __restrict__ root,
                            const float* __restrict__ bias, float* __restrict__ acc) {
    int t = blockIdx.x * blockDim.x + threadIdx.x;
    if (t >= NN * M_OUT) return;
    int n = t / M_OUT, o = t - n * M_OUT;
    const float* xr = x + n * M_IN;
    float s = bias[o];
#pragma unroll
    for (int i = 0; i < M_IN; i++) s = fmaf(xr[i], root[i * M_OUT + o], s);
    acc[t] = s;
}

__global__ void elu_kernel(const float* __restrict__ acc, float* __restrict__ xo, int n) {
    int t = blockIdx.x * blockDim.x + threadIdx.x;
    if (t < n) xo[t] = eluf(acc[t]);
}

// -------- message GEMM (fp16 mma, h plain + w2 hi/lo) + contract + scatter -
// V[e,n] = sum_k h16[e,k]*(wh[n,k] + wl[n,k]); av[e,o] += x[src_e,i(n)]*V[e,n];
// atomicAdd into acc[dst_e]. h error is per-edge random (cancels in pooling);
// w2 is exact to 2^-22 via the hi/lo split -> no systematic bias.
__device__ __forceinline__ void copyB(int c, uint32_t dst, int tid) {
    const unsigned char* gb = g_w2s + (size_t)c * 32768;
    for (int idx = tid; idx < 2048; idx += 256) {
        int half = idx >> 10, r = (idx >> 4) & 63, s = idx & 15;
        cp16(dst + half * SM_B_LO + r * 272 + s * 16, gb + half * 16384 + r * 256 + s * 16);
    }
}

template<int M_IN, int M_OUT, int NC>
__global__ void __launch_bounds__(256, 2)
msg_mma_kernel(const float* __restrict__ xin, float* __restrict__ acc) {
    extern __shared__ char smem[];
    const uint32_t sb = s2u(smem);
    const int tid = threadIdx.x, wid = tid >> 5, lane = tid & 31;

    // prologue: A + B0 as group0; B1 as group1
    {
        const unsigned char* ga = g_hA + (size_t)blockIdx.x * 32768;
        for (int idx = tid; idx < 2048; idx += 256) {
            int r = (idx >> 4) & 127, s = idx & 15;
            cp16(sb + r * 272 + s * 16, ga + r * 256 + s * 16);
        }
        copyB(0, sb + SM_B, tid);
        cp_commit();
        copyB(1, sb + SM_B + SM_BUF, tid);
        cp_commit();
    }

    const int m0 = wid * 16;
    const int r0 = lane >> 2;
    const int e0 = blockIdx.x * 128 + m0 + r0;
    const int e1 = e0 + 8;
    int src0 = 0, dst0 = -1, src1 = 0, dst1 = -1;
    if (e0 < NE) { src0 = g_src[e0]; dst0 = g_dst[e0]; }
    if (e1 < NE) { src1 = g_src[e1]; dst1 = g_dst[e1]; }

    const uint32_t lrow = (lane & 15);
    const uint32_t kh16 = (lane >> 4) * 16;

    float av[8][4];
#pragma unroll
    for (int nb = 0; nb < 8; nb++)
#pragma unroll
        for (int q = 0; q < 4; q++) av[nb][q] = 0.f;

    for (int c = 0; c < NC; c++) {
        if (c + 1 == NC) cp_wait<0>(); else cp_wait<1>();
        __syncthreads();

        const uint32_t bufb = sb + SM_B + (uint32_t)(c & 1) * SM_BUF;
        float d[8][4];
#pragma unroll
        for (int nb = 0; nb < 8; nb++)
#pragma unroll
            for (int q = 0; q < 4; q++) d[nb][q] = 0.f;

#pragma unroll
        for (int ks = 0; ks < 8; ks++) {
            uint32_t a[4];
            ldsm4(a, sb + (m0 + lrow) * 272 + ks * 32 + kh16);    // A loaded once
#pragma unroll
            for (int p = 0; p < 2; p++) {                          // B hi, then lo
                const uint32_t Bb = bufb + (uint32_t)p * SM_B_LO;
#pragma unroll
                for (int nb2 = 0; nb2 < 4; nb2++) {
                    uint32_t b[4];
                    ldsm4(b, Bb + (nb2 * 16 + lrow) * 272 + ks * 32 + kh16);
                    mma16816(d[2 * nb2],     a, b[0], b[2]);
                    mma16816(d[2 * nb2 + 1], a, b[1], b[3]);
                }
            }
        }

        // contract chunk with fp32 x
        if constexpr (M_OUT == 64) {
            const float xs0 = xin[(size_t)src0 * M_IN + c];
            const float xs1 = xin[(size_t)src1 * M_IN + c];
#pragma unroll
            for (int nb = 0; nb < 8; nb++) {
                av[nb][0] = fmaf(xs0, d[nb][0], av[nb][0]);
                av[nb][1] = fmaf(xs0, d[nb][1], av[nb][1]);
                av[nb][2] = fmaf(xs1, d[nb][2], av[nb][2]);
                av[nb][3] = fmaf(xs1, d[nb][3], av[nb][3]);
            }
        } else {
            const int i0 = min(2 * c, M_IN - 1), i1 = min(2 * c + 1, M_IN - 1);
            const float x00 = xin[(size_t)src0 * M_IN + i0];
            const float x01 = xin[(size_t)src0 * M_IN + i1];
            const float x10 = xin[(size_t)src1 * M_IN + i0];
            const float x11 = xin[(size_t)src1 * M_IN + i1];
#pragma unroll
            for (int nb = 0; nb < 8; nb++) {
                const float xsa = (nb < 4) ? x00 : x01;
                const float xsb = (nb < 4) ? x10 : x11;
                av[nb][0] = fmaf(xsa, d[nb][0], av[nb][0]);
                av[nb][1] = fmaf(xsa, d[nb][1], av[nb][1]);
                av[nb][2] = fmaf(xsb, d[nb][2], av[nb][2]);
                av[nb][3] = fmaf(xsb, d[nb][3], av[nb][3]);
            }
        }

        __syncthreads();                 // all warps done reading buf before refill
        if (c + 2 < NC) { copyB(c + 2, sb + SM_B + (uint32_t)(c & 1) * SM_BUF, tid); cp_commit(); }
    }

    // scatter-add (+ precomputed x@b2 term)
    const int oc = (lane & 3) * 2;
    if constexpr (M_OUT == 64) {
#pragma unroll
        for (int nb = 0; nb < 8; nb++) {
            const int o = nb * 8 + oc;
            if (dst0 >= 0) {
                atomicAdd(acc + (size_t)dst0 * 64 + o,     av[nb][0] + g_y[(size_t)src0 * 64 + o]);
                atomicAdd(acc + (size_t)dst0 * 64 + o + 1, av[nb][1] + g_y[(size_t)src0 * 64 + o + 1]);
            }
            if (dst1 >= 0) {
                atomicAdd(acc + (size_t)dst1 * 64 + o,     av[nb][2] + g_y[(size_t)src1 * 64 + o]);
                atomicAdd(acc + (size_t)dst1 * 64 + o + 1, av[nb][3] + g_y[(size_t)src1 * 64 + o + 1]);
            }
        }
    } else {
#pragma unroll
        for (int nb = 0; nb < 4; nb++) {
            const int o = nb * 8 + oc;
            if (dst0 >= 0) {
                atomicAdd(acc + (size_t)dst0 * 32 + o,     av[nb][0] + av[nb + 4][0] + g_y[(size_t)src0 * 32 + o]);
                atomicAdd(acc + (size_t)dst0 * 32 + o + 1, av[nb][1] + av[nb + 4][1] + g_y[(size_t)src0 * 32 + o + 1]);
            }
            if (dst1 >= 0) {
                atomicAdd(acc + (size_t)dst1 * 32 + o,     av[nb][2] + av[nb + 4][2] + g_y[(size_t)src1 * 32 + o]);
                atomicAdd(acc + (size_t)dst1 * 32 + o + 1, av[nb][3] + av[nb + 4][3] + g_y[(size_t)src1 * 32 + o + 1]);
            }
        }
    }
}

// ---------------- pooling + final MLP --------------------------------------
__global__ void pool_init_kernel() {
    int t = blockIdx.x * blockDim.x + threadIdx.x;
    if (t < NG * 64) g_sums[t] = 0.f;
    if (t < NG) g_cnt[t] = 0.f;
}
__global__ void pool_kernel(const float* __restrict__ x) {
    int t = blockIdx.x * blockDim.x + threadIdx.x;
    if (t >= NN * 64) return;
    int n = t >> 6, o = t & 63;
    int g = g_batch[n];
    atomicAdd(&g_sums[g * 64 + o], x[t]);
    if (o == 0) atomicAdd(&g_cnt[g], 1.f);
}
__global__ void __launch_bounds__(128)
mlp_kernel(const float* __restrict__ f1w, const float* __restrict__ f1b,
           const float* __restrict__ f2w, const float* __restrict__ f2b,
           const float* __restrict__ f3w, const float* __restrict__ f3b,
           float* __restrict__ out) {
    int g = blockIdx.x * blockDim.x + threadIdx.x;
    if (g >= NG) return;
    float inv = 1.f / fmaxf(g_cnt[g], 1.f);
    const float* sr = g_sums + g * 64;
    float h1[32];
#pragma unroll
    for (int j = 0; j < 32; j++) {
        float s = 0.f;
#pragma unroll
        for (int i = 0; i < 64; i++) s = fmaf(sr[i], f1w[i * 32 + j], s);
        h1[j] = eluf(fmaf(s, inv, f1b[j]));
    }
    float h2[16];
#pragma unroll
    for (int j = 0; j < 16; j++) {
        float s = f2b[j];
#pragma unroll
        for (int i = 0; i < 32; i++) s = fmaf(h1[i], f2w[i * 16 + j], s);
        h2[j] = eluf(s);
    }
    float s = f3b[0];
#pragma unroll
    for (int i = 0; i < 16; i++) s = fmaf(h2[i], f3w[i], s);
    out[g] = s;
}

// ---------------- driver ----------------------------------------------------
extern "C" void kernel_launch(void* const* d_in, const int* in_sizes, int n_in,
                              void* d_out, int out_size) {
    const float* x   = (const float*)d_in[0];
    const void*  ei  = d_in[1];
    const float* ea  = (const float*)d_in[2];
    const void*  bat = d_in[3];
    const float* W[24];
    for (int i = 0; i < 24; i++) W[i] = (const float*)d_in[4 + i];
    float* out = (float*)d_out;

    float *fa, *fb, *acc;
    cudaGetSymbolAddress((void**)&fa, g_fa);
    cudaGetSymbolAddress((void**)&fb, g_fb);
    cudaGetSymbolAddress((void**)&acc, g_acc);

    cudaFuncSetAttribute(msg_mma_kernel<13, 32, 7>,  cudaFuncAttributeMaxDynamicSharedMemorySize, SMEM_BYTES);
    cudaFuncSetAttribute(msg_mma_kernel<32, 64, 32>, cudaFuncAttributeMaxDynamicSharedMemorySize, SMEM_BYTES);
    cudaFuncSetAttribute(msg_mma_kernel<64, 64, 64>, cudaFuncAttributeMaxDynamicSharedMemorySize, SMEM_BYTES);

    detect_kernel<<<1, 32>>>((const long long*)ei);
    convert_kernel<<<(NE + 255) / 256, 256>>>(ei, bat);

    // layer 1: 13 -> 32
    edge_hA_kernel<<<(NE * 64 + 255) / 256, 256>>>(ea, W[0], W[1]);
    w2prep_kernel<13, 32, 7><<<(7 * 8192 + 255) / 256, 256>>>(W[2]);
    xb2_kernel<13, 32><<<(NN * 32 + 255) / 256, 256>>>(x, W[3]);
    root_kernel<13, 32><<<(NN * 32 + 255) / 256, 256>>>(x, W[4], W[5], acc);
    msg_mma_kernel<13, 32, 7><<<NTILES, 256, SMEM_BYTES>>>(x, acc);
    elu_kernel<<<(NN * 32 + 255) / 256, 256>>>(acc, fa, NN * 32);

    // layer 2: 32 -> 64
    edge_hA_kernel<<<(NE * 64 + 255) / 256, 256>>>(ea, W[6], W[7]);
    w2prep_kernel<32, 64, 32><<<(32 * 8192 + 255) / 256, 256>>>(W[8]);
    xb2_kernel<32, 64><<<(NN * 64 + 255) / 256, 256>>>(fa, W[9]);
    root_kernel<32, 64><<<(NN * 64 + 255) / 256, 256>>>(fa, W[10], W[11], acc);
    msg_mma_kernel<32, 64, 32><<<NTILES, 256, SMEM_BYTES>>>(fa, acc);
    elu_kernel<<<(NN * 64 + 255) / 256, 256>>>(acc, fb, NN * 64);

    // layer 3: 64 -> 64
    edge_hA_kernel<<<(NE * 64 + 255) / 256, 256>>>(ea, W[12], W[13]);
    w2prep_kernel<64, 64, 64><<<(64 * 8192 + 255) / 256, 256>>>(W[14]);
    xb2_kernel<64, 64><<<(NN * 64 + 255) / 256, 256>>>(fb, W[15]);
    root_kernel<64, 64><<<(NN * 64 + 255) / 256, 256>>>(fb, W[16], W[17], acc);
    msg_mma_kernel<64, 64, 64><<<NTILES, 256, SMEM_BYTES>>>(fb, acc);
    elu_kernel<<<(NN * 64 + 255) / 256, 256>>>(acc, fa, NN * 64);

    // pooling + head
    pool_init_kernel<<<(NG * 64 + 255) / 256, 256>>>();
    pool_kernel<<<(NN * 64 + 255) / 256, 256>>>(fa);
    mlp_kernel<<<(NG + 127) / 128, 128>>>(W[18], W[19], W[20], W[21], W[22], W[23], out);
}

// round 7
// speedup vs baseline: 10.0330x; 1.5569x over previous
#include <cuda_runtime.h>
#include <cuda_fp16.h>
#include <math.h>
#include <stdint.h>

#define NE 50000
#define NN 25000
#define NG 1024
#define HID 128
#define NTILES 391

// smem layout (dynamic): A [128x272B] | B buf0 [64x272B] | B buf1
#define SM_B      34816          // 128*272
#define SM_BUF    17408          // 64*272
#define SMEM_BYTES 69632

__device__ __align__(256) unsigned char g_hA[(size_t)NTILES * 32768]; // per-tile fp16 h [128x256B]
__device__ __align__(256) unsigned char g_w2s[64 * 16384];            // per-chunk fp16 w2T [64x256B]
__device__ float g_fa[NN * 64];
__device__ float g_fb[NN * 64];
__device__ float g_acc[NN * 64];
__device__ float g_y[NN * 64];        // x @ b2 per node
__device__ float g_sums[NG * 64];
__device__ float g_cnt[NG];
__device__ int g_src[NE], g_dst[NE], g_batch[NN], g_is64;

__device__ __forceinline__ float eluf(float v) { return v > 0.f ? v : expm1f(v); }
__device__ __forceinline__ uint32_t s2u(const void* p) {
    uint32_t a;
    asm("{ .reg .u64 t; cvta.to.shared.u64 t, %1; cvt.u32.u64 %0, t; }" : "=r"(a) : "l"(p));
    return a;
}
__device__ __forceinline__ void cp16(uint32_t s, const void* g) {
    asm volatile("cp.async.cg.shared.global [%0], [%1], 16;" :: "r"(s), "l"(g));
}
__device__ __forceinline__ void cp_commit() { asm volatile("cp.async.commit_group;" ::: "memory"); }
template<int N> __device__ __forceinline__ void cp_wait() { asm volatile("cp.async.wait_group %0;" :: "n"(N) : "memory"); }
__device__ __forceinline__ void ldsm4(uint32_t* r, uint32_t a) {
    asm volatile("ldmatrix.sync.aligned.m8n8.x4.shared.b16 {%0,%1,%2,%3}, [%4];"
                 : "=r"(r[0]), "=r"(r[1]), "=r"(r[2]), "=r"(r[3]) : "r"(a));
}
__device__ __forceinline__ void mma16816(float* d, const uint32_t* a, uint32_t b0, uint32_t b1) {
    asm volatile("mma.sync.aligned.m16n8k16.row.col.f32.f16.f16.f32 "
                 "{%0,%1,%2,%3}, {%4,%5,%6,%7}, {%8,%9}, {%0,%1,%2,%3};"
                 : "+f"(d[0]), "+f"(d[1]), "+f"(d[2]), "+f"(d[3])
                 : "r"(a[0]), "r"(a[1]), "r"(a[2]), "r"(a[3]), "r"(b0), "r"(b1));
}

// ---------------- index dtype detect + convert -----------------------------
__global__ void detect_kernel(const long long* __restrict__ ei) {
    if (blockIdx.x == 0 && threadIdx.x == 0) {
        int is64 = 1;
        for (int i = 0; i < 256; i++) { long long v = ei[i]; if (v < 0 || v >= (long long)NN) { is64 = 0; break; } }
        g_is64 = is64;
    }
}
__global__ void convert_kernel(const void* __restrict__ ei, const void* __restrict__ bat) {
    int t = blockIdx.x * blockDim.x + threadIdx.x;
    const int is64 = g_is64;
    if (t < NE) {
        if (is64) { g_src[t] = (int)((const long long*)ei)[t]; g_dst[t] = (int)((const long long*)ei)[NE + t]; }
        else      { g_src[t] = ((const int*)ei)[t];            g_dst[t] = ((const int*)ei)[NE + t]; }
    }
    if (t < NN) g_batch[t] = is64 ? (int)((const long long*)bat)[t] : ((const int*)bat)[t];
}

__global__ void pool_init_kernel() {
    int t = blockIdx.x * blockDim.x + threadIdx.x;
    if (t < NG * 64) g_sums[t] = 0.f;
    if (t < NG) g_cnt[t] = 0.f;
}

// -------- edge MLP -> fp16 A tiles (per 128-edge tile, row-major 256B) -----
__global__ void edge_hA_kernel(const float* __restrict__ ea, const float* __restrict__ w1,
                               const float* __restrict__ b1) {
    int t = blockIdx.x * blockDim.x + threadIdx.x;
    if (t >= NE * 64) return;
    int e = t >> 6, k = (t & 63) * 2;
    const float* a = ea + e * 5;
    float s0 = b1[k], s1 = b1[k + 1];
#pragma unroll
    for (int d = 0; d < 5; d++) { float av = a[d]; s0 = fmaf(av, w1[d * HID + k], s0); s1 = fmaf(av, w1[d * HID + k + 1], s1); }
    s0 = fmaxf(s0, 0.f); s1 = fmaxf(s1, 0.f);
    __half h0 = __float2half(s0), h1 = __float2half(s1);
    int tile = e >> 7, row = e & 127;
    unsigned char* base = g_hA + (size_t)tile * 32768;
    *(uint32_t*)(base + row * 256 + k * 2) =
        ((uint32_t)__half_as_ushort(h1) << 16) | __half_as_ushort(h0);
}

// -------- w2 -> fp16 B chunk tiles: w2T[n][k], 64 n-rows per chunk ---------
template<int M_IN, int M_OUT, int NC>
__global__ void w2prep_kernel(const float* __restrict__ w2) {
    int t = blockIdx.x * blockDim.x + threadIdx.x;
    if (t >= NC * 8192) return;
    int c = t >> 13, rem = t & 8191, r = rem >> 7, k = rem & 127;
    int n = c * 64 + r;
    float v = (n < M_IN * M_OUT) ? w2[k * (M_IN * M_OUT) + n] : 0.f;
    *(__half*)(g_w2s + (size_t)c * 16384 + r * 256 + k * 2) = __float2half(v);
}

// -------- acc = x @ root + bias;  g_y = x @ b2  (fused, one x-row read) ----
template<int M_IN, int M_OUT>
__global__ void rootxb2_kernel(const float* __restrict__ x, const float* __restrict__ root,
                               const float* __restrict__ bias, const float* __restrict__ b2,
                               float* __restrict__ acc) {
    int t = blockIdx.x * blockDim.x + threadIdx.x;
    if (t >= NN * M_OUT) return;
    int n = t / M_OUT, o = t - n * M_OUT;
    const float* xr = x + n * M_IN;
    float s = bias[o], y = 0.f;
#pragma unroll
    for (int i = 0; i < M_IN; i++) {
        float xv = xr[i];
        s = fmaf(xv, root[i * M_OUT + o], s);
        y = fmaf(xv, b2[i * M_OUT + o], y);
    }
    acc[t] = s;
    g_y[t] = y;
}

__global__ void elu_kernel(const float* __restrict__ acc, float* __restrict__ xo, int n) {
    int t = blockIdx.x * blockDim.x + threadIdx.x;
    if (t < n) xo[t] = eluf(acc[t]);
}

// -------- layer-3 elu fused with graph pooling (features never stored) -----
__global__ void elu_pool_kernel(const float* __restrict__ acc) {
    int t = blockIdx.x * blockDim.x + threadIdx.x;
    if (t >= NN * 64) return;
    int n = t >> 6, o = t & 63;
    float v = eluf(acc[t]);
    int g = g_batch[n];
    atomicAdd(&g_sums[g * 64 + o], v);
    if (o == 0) atomicAdd(&g_cnt[g], 1.f);
}

// -------- message GEMM (fp16 mma, single pass) + contract + scatter --------
// V[e,n] = sum_k h16[e,k]*w16[n,k]; av[e,o] += x[src_e,i(n)]*V[e,n];
// atomicAdd into acc[dst_e]. fp16 rounding of h and w2 is ~2^-12 relative,
// pseudo-random element-wise -> measured transfer to final output ~0.004-0.03
// => final rel_err ~1e-5, far under the 1e-3 gate.
__device__ __forceinline__ void copyB(int c, uint32_t dst, int tid) {
    const unsigned char* gb = g_w2s + (size_t)c * 16384;
    for (int idx = tid; idx < 1024; idx += 256) {
        int r = idx >> 4, s = idx & 15;
        cp16(dst + r * 272 + s * 16, gb + r * 256 + s * 16);
    }
}

template<int M_IN, int M_OUT, int NC>
__global__ void __launch_bounds__(256, 2)
msg_mma_kernel(const float* __restrict__ xin, float* __restrict__ acc) {
    extern __shared__ char smem[];
    const uint32_t sb = s2u(smem);
    const int tid = threadIdx.x, wid = tid >> 5, lane = tid & 31;

    // prologue: A + B0 as group0; B1 as group1
    {
        const unsigned char* ga = g_hA + (size_t)blockIdx.x * 32768;
        for (int idx = tid; idx < 2048; idx += 256) {
            int r = (idx >> 4) & 127, s = idx & 15;
            cp16(sb + r * 272 + s * 16, ga + r * 256 + s * 16);
        }
        copyB(0, sb + SM_B, tid);
        cp_commit();
        if (NC > 1) { copyB(1, sb + SM_B + SM_BUF, tid); cp_commit(); }
    }

    const int m0 = wid * 16;
    const int r0 = lane >> 2;
    const int e0 = blockIdx.x * 128 + m0 + r0;
    const int e1 = e0 + 8;
    int src0 = 0, dst0 = -1, src1 = 0, dst1 = -1;
    if (e0 < NE) { src0 = g_src[e0]; dst0 = g_dst[e0]; }
    if (e1 < NE) { src1 = g_src[e1]; dst1 = g_dst[e1]; }

    const uint32_t lrow = (lane & 15);
    const uint32_t kh16 = (lane >> 4) * 16;

    float av[8][4];
#pragma unroll
    for (int nb = 0; nb < 8; nb++)
#pragma unroll
        for (int q = 0; q < 4; q++) av[nb][q] = 0.f;

    for (int c = 0; c < NC; c++) {
        if (c + 1 == NC) cp_wait<0>(); else cp_wait<1>();
        __syncthreads();

        const uint32_t Bb = sb + SM_B + (uint32_t)(c & 1) * SM_BUF;
        float d[8][4];
#pragma unroll
        for (int nb = 0; nb < 8; nb++)
#pragma unroll
            for (int q = 0; q < 4; q++) d[nb][q] = 0.f;

#pragma unroll
        for (int ks = 0; ks < 8; ks++) {
            uint32_t a[4];
            ldsm4(a, sb + (m0 + lrow) * 272 + ks * 32 + kh16);
#pragma unroll
            for (int nb2 = 0; nb2 < 4; nb2++) {
                uint32_t b[4];
                ldsm4(b, Bb + (nb2 * 16 + lrow) * 272 + ks * 32 + kh16);
                mma16816(d[2 * nb2],     a, b[0], b[2]);
                mma16816(d[2 * nb2 + 1], a, b[1], b[3]);
            }
        }

        // contract chunk with fp32 x
        if constexpr (M_OUT == 64) {
            const float xs0 = xin[(size_t)src0 * M_IN + c];
            const float xs1 = xin[(size_t)src1 * M_IN + c];
#pragma unroll
            for (int nb = 0; nb < 8; nb++) {
                av[nb][0] = fmaf(xs0, d[nb][0], av[nb][0]);
                av[nb][1] = fmaf(xs0, d[nb][1], av[nb][1]);
                av[nb][2] = fmaf(xs1, d[nb][2], av[nb][2]);
                av[nb][3] = fmaf(xs1, d[nb][3], av[nb][3]);
            }
        } else {
            const int i0 = min(2 * c, M_IN - 1), i1 = min(2 * c + 1, M_IN - 1);
            const float x00 = xin[(size_t)src0 * M_IN + i0];
            const float x01 = xin[(size_t)src0 * M_IN + i1];
            const float x10 = xin[(size_t)src1 * M_IN + i0];
            const float x11 = xin[(size_t)src1 * M_IN + i1];
#pragma unroll
            for (int nb = 0; nb < 8; nb++) {
                const float xsa = (nb < 4) ? x00 : x01;
                const float xsb = (nb < 4) ? x10 : x11;
                av[nb][0] = fmaf(xsa, d[nb][0], av[nb][0]);
                av[nb][1] = fmaf(xsa, d[nb][1], av[nb][1]);
                av[nb][2] = fmaf(xsb, d[nb][2], av[nb][2]);
                av[nb][3] = fmaf(xsb, d[nb][3], av[nb][3]);
            }
        }

        __syncthreads();                 // all warps done reading buf before refill
        if (c + 2 < NC) { copyB(c + 2, sb + SM_B + (uint32_t)(c & 1) * SM_BUF, tid); cp_commit(); }
    }

    // scatter-add (+ precomputed x@b2 term)
    const int oc = (lane & 3) * 2;
    if constexpr (M_OUT == 64) {
#pragma unroll
        for (int nb = 0; nb < 8; nb++) {
            const int o = nb * 8 + oc;
            if (dst0 >= 0) {
                atomicAdd(acc + (size_t)dst0 * 64 + o,     av[nb][0] + g_y[(size_t)src0 * 64 + o]);
                atomicAdd(acc + (size_t)dst0 * 64 + o + 1, av[nb][1] + g_y[(size_t)src0 * 64 + o + 1]);
            }
            if (dst1 >= 0) {
                atomicAdd(acc + (size_t)dst1 * 64 + o,     av[nb][2] + g_y[(size_t)src1 * 64 + o]);
                atomicAdd(acc + (size_t)dst1 * 64 + o + 1, av[nb][3] + g_y[(size_t)src1 * 64 + o + 1]);
            }
        }
    } else {
#pragma unroll
        for (int nb = 0; nb < 4; nb++) {
            const int o = nb * 8 + oc;
            if (dst0 >= 0) {
                atomicAdd(acc + (size_t)dst0 * 32 + o,     av[nb][0] + av[nb + 4][0] + g_y[(size_t)src0 * 32 + o]);
                atomicAdd(acc + (size_t)dst0 * 32 + o + 1, av[nb][1] + av[nb + 4][1] + g_y[(size_t)src0 * 32 + o + 1]);
            }
            if (dst1 >= 0) {
                atomicAdd(acc + (size_t)dst1 * 32 + o,     av[nb][2] + av[nb + 4][2] + g_y[(size_t)src1 * 32 + o]);
                atomicAdd(acc + (size_t)dst1 * 32 + o + 1, av[nb][3] + av[nb + 4][3] + g_y[(size_t)src1 * 32 + o + 1]);
            }
        }
    }
}

// ---------------- final MLP -------------------------------------------------
__global__ void __launch_bounds__(128)
mlp_kernel(const float* __restrict__ f1w, const float* __restrict__ f1b,
           const float* __restrict__ f2w, const float* __restrict__ f2b,
           const float* __restrict__ f3w, const float* __restrict__ f3b,
           float* __restrict__ out) {
    int g = blockIdx.x * blockDim.x + threadIdx.x;
    if (g >= NG) return;
    float inv = 1.f / fmaxf(g_cnt[g], 1.f);
    const float* sr = g_sums + g * 64;
    float h1[32];
#pragma unroll
    for (int j = 0; j < 32; j++) {
        float s = 0.f;
#pragma unroll
        for (int i = 0; i < 64; i++) s = fmaf(sr[i], f1w[i * 32 + j], s);
        h1[j] = eluf(fmaf(s, inv, f1b[j]));
    }
    float h2[16];
#pragma unroll
    for (int j = 0; j < 16; j++) {
        float s = f2b[j];
#pragma unroll
        for (int i = 0; i < 32; i++) s = fmaf(h1[i], f2w[i * 16 + j], s);
        h2[j] = eluf(s);
    }
    float s = f3b[0];
#pragma unroll
    for (int i = 0; i < 16; i++) s = fmaf(h2[i], f3w[i], s);
    out[g] = s;
}

// ---------------- driver ----------------------------------------------------
extern "C" void kernel_launch(void* const* d_in, const int* in_sizes, int n_in,
                              void* d_out, int out_size) {
    const float* x   = (const float*)d_in[0];
    const void*  ei  = d_in[1];
    const float* ea  = (const float*)d_in[2];
    const void*  bat = d_in[3];
    const float* W[24];
    for (int i = 0; i < 24; i++) W[i] = (const float*)d_in[4 + i];
    float* out = (float*)d_out;

    float *fa, *fb, *acc;
    cudaGetSymbolAddress((void**)&fa, g_fa);
    cudaGetSymbolAddress((void**)&fb, g_fb);
    cudaGetSymbolAddress((void**)&acc, g_acc);

    cudaFuncSetAttribute(msg_mma_kernel<13, 32, 7>,  cudaFuncAttributeMaxDynamicSharedMemorySize, SMEM_BYTES);
    cudaFuncSetAttribute(msg_mma_kernel<32, 64, 32>, cudaFuncAttributeMaxDynamicSharedMemorySize, SMEM_BYTES);
    cudaFuncSetAttribute(msg_mma_kernel<64, 64, 64>, cudaFuncAttributeMaxDynamicSharedMemorySize, SMEM_BYTES);

    detect_kernel<<<1, 32>>>((const long long*)ei);
    convert_kernel<<<(NE + 255) / 256, 256>>>(ei, bat);
    pool_init_kernel<<<(NG * 64 + 255) / 256, 256>>>();

    // layer 1: 13 -> 32
    edge_hA_kernel<<<(NE * 64 + 255) / 256, 256>>>(ea, W[0], W[1]);
    w2prep_kernel<13, 32, 7><<<(7 * 8192 + 255) / 256, 256>>>(W[2]);
    rootxb2_kernel<13, 32><<<(NN * 32 + 255) / 256, 256>>>(x, W[4], W[5], W[3], acc);
    msg_mma_kernel<13, 32, 7><<<NTILES, 256, SMEM_BYTES>>>(x, acc);
    elu_kernel<<<(NN * 32 + 255) / 256, 256>>>(acc, fa, NN * 32);

    // layer 2: 32 -> 64
    edge_hA_kernel<<<(NE * 64 + 255) / 256, 256>>>(ea, W[6], W[7]);
    w2prep_kernel<32, 64, 32><<<(32 * 8192 + 255) / 256, 256>>>(W[8]);
    rootxb2_kernel<32, 64><<<(NN * 64 + 255) / 256, 256>>>(fa, W[10], W[11], W[9], acc);
    msg_mma_kernel<32, 64, 32><<<NTILES, 256, SMEM_BYTES>>>(fa, acc);
    elu_kernel<<<(NN * 64 + 255) / 256, 256>>>(acc, fb, NN * 64);

    // layer 3: 64 -> 64 (elu fused with pooling; features never stored)
    edge_hA_kernel<<<(NE * 64 + 255) / 256, 256>>>(ea, W[12], W[13]);
    w2prep_kernel<64, 64, 64><<<(64 * 8192 + 255) / 256, 256>>>(W[14]);
    rootxb2_kernel<64, 64><<<(NN * 64 + 255) / 256, 256>>>(fb, W[16], W[17], W[15], acc);
    msg_mma_kernel<64, 64, 64><<<NTILES, 256, SMEM_BYTES>>>(fb, acc);
    elu_pool_kernel<<<(NN * 64 + 255) / 256, 256>>>(acc);

    // head
    mlp_kernel<<<(NG + 127) / 128, 128>>>(W[18], W[19], W[20], W[21], W[22], W[23], out);
}